// round 14
// baseline (speedup 1.0000x reference)
#include <cuda_runtime.h>
#include <cuda_bf16.h>
#include <cuda_fp16.h>
#include <cuda_fp8.h>
#include <math.h>
#include <stdint.h>

#define B_    64
#define S_    512
#define H_    1024
#define HD2   512
#define L_    9
#define NTOK  (B_*S_)
#define EPS_  1e-5f
#define LOG2E_ 1.4426950408889634f
#define LN2_   0.6931471805599453f
#define W1SCL  64.0f
#define W1INV  0.015625f

// ---------------- device scratch (no allocation allowed) -------------------
__device__ uint8_t g_x8[(size_t)NTOK * H_];          // LN-normalized X, e4m3
__device__ uint8_t g_w1t8[(size_t)HD2 * H_];         // (W1*64)^T e4m3 [N][K]
__device__ float g_emp[4][(size_t)NTOK * L_];        // partial emissions per n-slice
__device__ float g_llh[B_];

// ---------------------------------------------------------------------------
__device__ __forceinline__ float ex2f_(float x){ float y; asm("ex2.approx.ftz.f32 %0,%1;":"=f"(y):"f"(x)); return y; }
__device__ __forceinline__ float lg2f_(float x){ float y; asm("lg2.approx.ftz.f32 %0,%1;":"=f"(y):"f"(x)); return y; }

__device__ __forceinline__ void cp16s(uint32_t dst, const void* src){
    asm volatile("cp.async.cg.shared.global [%0], [%1], 16;" :: "r"(dst), "l"(src));
}
__device__ __forceinline__ void ldsm4(uint32_t* r, uint32_t addr){
    asm volatile("ldmatrix.sync.aligned.m8n8.x4.shared.b16 {%0,%1,%2,%3}, [%4];"
        : "=r"(r[0]), "=r"(r[1]), "=r"(r[2]), "=r"(r[3]) : "r"(addr));
}
__device__ __forceinline__ uint16_t f2e4m3x2_(float hi, float lo){
    uint16_t r;
    asm("cvt.rn.satfinite.e4m3x2.f32 %0, %1, %2;" : "=h"(r) : "f"(hi), "f"(lo));
    return r;
}
// tanh-form GELU: overflow-safe (ez=inf -> th=1), ~0.1-0.3% off exact erf GELU,
// far below the fp8 quantization noise already present.
__device__ __forceinline__ float gelu_(float c){
    float u  = 0.7978845608028654f * fmaf(0.044715f * c, c * c, c);
    float ez = ex2f_(u * 2.8853900817779268f);          // e^{2u}
    float th = 1.0f - __fdividef(2.0f, ez + 1.0f);
    return 0.5f * c * (1.0f + th);
}

// ---------------------------------------------------------------------------
// Kernel 1: LayerNorm -> normalized e4m3 X. Warp-per-row, barrier-free.
// ---------------------------------------------------------------------------
__global__ void __launch_bounds__(256) ln_norm_kernel(
    const float* __restrict__ hs,
    const float* __restrict__ gamma,
    const float* __restrict__ beta)
{
    const int warp = threadIdx.x >> 5;
    const int lane = threadIdx.x & 31;

    #pragma unroll
    for (int rr = 0; rr < 4; rr++) {
        const int row = blockIdx.x * 32 + warp * 4 + rr;
        const float4* p = (const float4*)(hs + (size_t)row * H_);
        float4 v[8];
        float s = 0.f, ss = 0.f;
        #pragma unroll
        for (int j = 0; j < 8; j++) {
            v[j] = p[lane + 32 * j];
            s  += v[j].x + v[j].y + v[j].z + v[j].w;
            ss += v[j].x*v[j].x + v[j].y*v[j].y + v[j].z*v[j].z + v[j].w*v[j].w;
        }
        #pragma unroll
        for (int off = 16; off; off >>= 1) {
            s  += __shfl_xor_sync(0xffffffffu, s,  off);
            ss += __shfl_xor_sync(0xffffffffu, ss, off);
        }
        const float mu   = s * (1.0f / H_);
        const float rstd = rsqrtf(ss * (1.0f / H_) - mu * mu + EPS_);

        uint32_t* dst = (uint32_t*)(g_x8 + (size_t)row * H_);
        #pragma unroll
        for (int j = 0; j < 8; j++) {
            const int q = lane + 32 * j;
            float4 g4 = ((const float4*)gamma)[q];
            float4 b4 = ((const float4*)beta)[q];
            float o0 = (v[j].x - mu) * rstd * g4.x + b4.x;
            float o1 = (v[j].y - mu) * rstd * g4.y + b4.y;
            float o2 = (v[j].z - mu) * rstd * g4.z + b4.z;
            float o3 = (v[j].w - mu) * rstd * g4.w + b4.w;
            uint32_t lo = f2e4m3x2_(o1, o0);
            uint32_t hi = f2e4m3x2_(o3, o2);
            dst[q] = lo | (hi << 16);
        }
    }
}

// ---------------------------------------------------------------------------
// Kernel 2: W1 [K=1024][N=512] fp32 -> (W1*64)^T e4m3 [N][K]
// ---------------------------------------------------------------------------
__global__ void w1_transpose_kernel(const float* __restrict__ W1)
{
    __shared__ float tile[32][33];
    const int n0 = blockIdx.x * 32, k0 = blockIdx.y * 32;
    const int tx = threadIdx.x, ty = threadIdx.y;   // (32, 8)
    #pragma unroll
    for (int i = 0; i < 4; i++)
        tile[ty + 8*i][tx] = W1[(size_t)(k0 + ty + 8*i) * HD2 + n0 + tx];
    __syncthreads();
    #pragma unroll
    for (int i = 0; i < 4; i++) {
        uint16_t p = f2e4m3x2_(0.f, tile[tx][ty + 8*i] * W1SCL);
        g_w1t8[(size_t)(n0 + ty + 8*i) * H_ + k0 + tx] = (uint8_t)(p & 0xff);
    }
}

// ---------------------------------------------------------------------------
// Kernel 3: FUSED GEMM1+GELU+GEMM2-partial (R11/R13 structure).
// ---------------------------------------------------------------------------
#define ROWB    80                       // 64B data + 16B pad
#define TILE_A  (128 * ROWB)             // 10240
#define TILE_BB (128 * ROWB)             // 10240
#define STG_B   (TILE_A + TILE_BB)       // 20480
#define NSTG    3
#define NKT     16                       // 1024B / 64B
#define PIPE_B  (NSTG * STG_B)           // 61440
#define W2_OFF  PIPE_B                   // [128][12] floats = 6144 B
#define B1_OFF  (W2_OFF + 6144)          // 128 floats = 512 B
#define STGRED  (B1_OFF + 512)           // [4][32][12] floats = 6144 B
#define GEMM1_SMEM (STGRED + 6144)       // 74240

__global__ void __launch_bounds__(256, 3) gemm1_tc_kernel(
    const float* __restrict__ b1, const float* __restrict__ W2)
{
    extern __shared__ __align__(16) char dsm[];
    const uint32_t sbase = (uint32_t)__cvta_generic_to_shared(dsm);
    float* w2s = (float*)(dsm + W2_OFF);     // [128][12]
    float* b1s = (float*)(dsm + B1_OFF);     // [128]
    float* stg = (float*)(dsm + STGRED);     // [4][32][12]

    const int tid  = threadIdx.x;
    const int m0   = blockIdx.y * 128;
    const int n0   = blockIdx.x * 128;       // h-col slice base
    const int warp = tid >> 5, lane = tid & 31;
    const int wm   = warp & 1;               // M half (64 rows)
    const int wn   = warp >> 1;              // N quarter (32 cols)

    // preload W2 slice + b1 slice
    for (int i = tid; i < 128 * L_; i += 256)
        w2s[(i / L_) * 12 + (i % L_)] = W2[(size_t)(n0 + i / L_) * L_ + (i % L_)];
    if (tid < 128) b1s[tid] = b1[n0 + tid];

    uint32_t offA[4], offB[2];
    {
        const int rA = (lane & 15);
        const int cA = (lane >> 4);
        #pragma unroll
        for (int mt = 0; mt < 4; mt++)
            offA[mt] = (uint32_t)((wm * 64 + mt * 16 + rA) * ROWB + cA * 16);
        const int rB = (lane & 7) + ((lane >> 4) << 3);
        const int cB = (lane >> 3) & 1;
        #pragma unroll
        for (int p = 0; p < 2; p++)
            offB[p] = (uint32_t)(TILE_A + (wn * 32 + p * 16 + rB) * ROWB + cB * 16);
    }

    // loaders: 1 thread per row; tid<128 -> A row, tid>=128 -> B row. 4x16B.
    const int lrow = tid & 127;
    const int isB  = tid >> 7;
    const uint8_t* Sg = isB ? (g_w1t8 + (size_t)(n0 + lrow) * H_)
                            : (g_x8   + (size_t)(m0 + lrow) * H_);
    const uint32_t dS = sbase + isB * TILE_A + lrow * ROWB;

    uint32_t acc[4][4][2];                 // f16x2 accumulators
    #pragma unroll
    for (int mt = 0; mt < 4; mt++)
        #pragma unroll
        for (int nt = 0; nt < 4; nt++) { acc[mt][nt][0] = 0u; acc[mt][nt][1] = 0u; }

    #pragma unroll
    for (int p = 0; p < 2; ++p) {
        const uint32_t sg = p * STG_B;
        #pragma unroll
        for (int c = 0; c < 4; c++)
            cp16s(dS + sg + c * 16, Sg + p * 64 + c * 16);
        asm volatile("cp.async.commit_group;");
    }

    for (int t = 0; t < NKT; ++t) {
        if (t < NKT - 1) asm volatile("cp.async.wait_group 1;");
        else             asm volatile("cp.async.wait_group 0;");
        __syncthreads();

        const uint32_t sS = sbase + (t % NSTG) * STG_B;
        #pragma unroll
        for (int kt = 0; kt < 2; ++kt) {            // two k32 steps per 64B row
            uint32_t a[4][4], b[2][4];
            #pragma unroll
            for (int mt = 0; mt < 4; mt++) ldsm4(a[mt], sS + offA[mt] + kt * 32);
            #pragma unroll
            for (int p = 0; p < 2; p++)    ldsm4(b[p],  sS + offB[p]  + kt * 32);
            #pragma unroll
            for (int mt = 0; mt < 4; mt++)
                #pragma unroll
                for (int nt = 0; nt < 4; nt++) {
                    const uint32_t b0  = b[nt >> 1][(nt & 1) * 2];
                    const uint32_t b1r = b[nt >> 1][(nt & 1) * 2 + 1];
                    asm volatile(
                        "mma.sync.aligned.m16n8k32.row.col.f16.e4m3.e4m3.f16 "
                        "{%0,%1},{%2,%3,%4,%5},{%6,%7},{%0,%1};"
                        : "+r"(acc[mt][nt][0]), "+r"(acc[mt][nt][1])
                        : "r"(a[mt][0]), "r"(a[mt][1]), "r"(a[mt][2]), "r"(a[mt][3]),
                          "r"(b0), "r"(b1r));
                }
        }

        if (t + 2 < NKT) {
            const uint32_t sg = ((t + 2) % NSTG) * STG_B;
            const int k0 = (t + 2) * 64;
            #pragma unroll
            for (int c = 0; c < 4; c++)
                cp16s(dS + sg + c * 16, Sg + k0 + c * 16);
            asm volatile("cp.async.commit_group;");
        }
    }

    // ---- fused epilogue: fast GELU + dot with W2 slice + staged reduction ----
    const int r = lane >> 2, tig = lane & 3;
    #pragma unroll
    for (int mt = 0; mt < 4; mt++) {
        float e0[L_], e1[L_];
        #pragma unroll
        for (int l = 0; l < L_; l++) { e0[l] = 0.f; e1[l] = 0.f; }

        #pragma unroll
        for (int nt = 0; nt < 4; nt++) {
            const int c0 = wn * 32 + nt * 8 + 2 * tig;   // local h-col
            const float bx = b1s[c0], by = b1s[c0 + 1];
            float2 f01 = __half22float2(*(__half2*)&acc[mt][nt][0]);
            float2 f23 = __half22float2(*(__half2*)&acc[mt][nt][1]);
            float g00 = gelu_(f01.x * W1INV + bx);
            float g01 = gelu_(f01.y * W1INV + by);
            float g10 = gelu_(f23.x * W1INV + bx);
            float g11 = gelu_(f23.y * W1INV + by);
            const float* w0 = &w2s[c0 * 12];
            const float* w1 = &w2s[(c0 + 1) * 12];
            #pragma unroll
            for (int l = 0; l < L_; l++) {
                e0[l] = fmaf(g00, w0[l], fmaf(g01, w1[l], e0[l]));
                e1[l] = fmaf(g10, w0[l], fmaf(g11, w1[l], e1[l]));
            }
        }
        #pragma unroll
        for (int l = 0; l < L_; l++) {
            e0[l] += __shfl_xor_sync(0xffffffffu, e0[l], 1);
            e0[l] += __shfl_xor_sync(0xffffffffu, e0[l], 2);
            e1[l] += __shfl_xor_sync(0xffffffffu, e1[l], 1);
            e1[l] += __shfl_xor_sync(0xffffffffu, e1[l], 2);
        }
        if (tig == 0) {
            float* s0 = &stg[(wn * 32 + wm * 16 + r) * 12];
            float* s1 = &stg[(wn * 32 + wm * 16 + r + 8) * 12];
            #pragma unroll
            for (int l = 0; l < L_; l++) { s0[l] = e0[l]; s1[l] = e1[l]; }
        }
        __syncthreads();
        for (int idx = tid; idx < 32 * L_; idx += 256) {
            const int wr = idx / L_, l = idx % L_;
            const int wmm = wr >> 4, rr = wr & 15;
            float v = stg[(0 * 32 + wr) * 12 + l] + stg[(1 * 32 + wr) * 12 + l]
                    + stg[(2 * 32 + wr) * 12 + l] + stg[(3 * 32 + wr) * 12 + l];
            const int row = m0 + wmm * 64 + mt * 16 + rr;
            g_emp[blockIdx.x][(size_t)row * L_ + l] = v;
        }
        __syncthreads();
    }
}

// ---------------------------------------------------------------------------
// Kernel 4: CRF with inline emission summation (em = sum of 4 slices + b2).
// Ballot masks; linear-space scan; deep prefetch of summed emissions.
// ---------------------------------------------------------------------------
__global__ void crf_kernel(const float* __restrict__ st,
                           const float* __restrict__ et,
                           const float* __restrict__ trans,
                           const float* __restrict__ b2,
                           const int*   __restrict__ labels,
                           const int*   __restrict__ am)
{
    const int b    = blockIdx.x;
    const int lane = threadIdx.x;
    const size_t base = (size_t)b * S_ * L_;
    const int* lab = labels + (size_t)b * S_;
    const int* amk = am     + (size_t)b * S_;

    uint32_t mword[16];
    #pragma unroll
    for (int c = 0; c < 16; c++) {
        int t = c * 32 + lane;
        int l = lab[t];
        bool mk = (l != -100) && (amk[t] == 1);
        mword[c] = __ballot_sync(0xffffffffu, mk);
    }

    // summed-emission gather
    #define EMV(t, l) (g_emp[0][base + (size_t)(t) * L_ + (l)] + \
                       g_emp[1][base + (size_t)(t) * L_ + (l)] + \
                       g_emp[2][base + (size_t)(t) * L_ + (l)] + \
                       g_emp[3][base + (size_t)(t) * L_ + (l)] + b2[l])

    // ---- numerator (lane-parallel) ----
    float part = 0.f;
    int   cnt  = 0;
    for (int t = lane; t < S_; t += 32) {
        bool rw = (mword[t >> 5] >> (t & 31)) & 1;
        bool mk = (t == 0) ? true : rw;
        if (mk) cnt++;
        if (t > 0 && rw) {
            int tp = lab[t - 1]; if (tp == -100) tp = 0;
            int tc = lab[t];     if (tc == -100) tc = 0;
            part += trans[tp * L_ + tc] + EMV(t, tc);
        }
    }
    #pragma unroll
    for (int off = 16; off; off >>= 1) {
        part += __shfl_down_sync(0xffffffffu, part, off);
        cnt  += __shfl_down_sync(0xffffffffu, cnt,  off);
    }
    float num = 0.f;
    if (lane == 0) {
        int tg0 = lab[0]; if (tg0 == -100) tg0 = 0;
        num = part + st[tg0] + EMV(0, tg0);
        int se = cnt - 1;
        int lt = lab[se]; if (lt == -100) lt = 0;
        num += et[lt];
    }

    // ---- denominator: linear-space scan, deep prefetch of summed em ----
    const int j = lane;
    float c_[L_];
    #pragma unroll
    for (int i = 0; i < L_; i++)
        c_[i] = (j < L_) ? ex2f_(trans[i * L_ + j] * LOG2E_) : 0.f;

    float p  = (j < L_) ? ex2f_((st[j] + EMV(0, j)) * LOG2E_) : 0.f;
    float C2 = 0.f;

    float cur[8], nxt[8];
    #pragma unroll
    for (int i = 0; i < 8; i++)
        cur[i] = (j < L_) ? EMV(1 + i, j) : 0.f;

    for (int tb = 1; tb < S_; tb += 8) {
        #pragma unroll
        for (int i = 0; i < 8; i++) {
            int tn = tb + 8 + i;
            nxt[i] = (tn < S_ && j < L_) ? EMV(tn, j) : 0.f;
        }
        {
            float m = __shfl_sync(0xffffffffu, p, 0);
            int e = (__float_as_int(m) >> 23) & 255;
            float sc = __int_as_float((254 - e) << 23);
            p *= sc;
            C2 += (float)(e - 127);
        }
        #pragma unroll
        for (int i = 0; i < 8; i++) {
            int t = tb + i;
            if (t < S_) {
                float eem = ex2f_(cur[i] * LOG2E_);
                float pa[L_];
                #pragma unroll
                for (int q = 0; q < L_; q++) pa[q] = __shfl_sync(0xffffffffu, p, q);
                float s01 = fmaf(pa[1], c_[1], pa[0] * c_[0]);
                float s23 = fmaf(pa[3], c_[3], pa[2] * c_[2]);
                float s45 = fmaf(pa[5], c_[5], pa[4] * c_[4]);
                float s67 = fmaf(pa[7], c_[7], pa[6] * c_[6]);
                float s8  = pa[8] * c_[8];
                float s   = (s01 + s23) + (s45 + s67) + s8;
                float pn  = s * eem;
                bool mk = (mword[t >> 5] >> (t & 31)) & 1;
                p = mk ? pn : p;
            }
        }
        #pragma unroll
        for (int i = 0; i < 8; i++) cur[i] = nxt[i];
    }
    #undef EMV

    float fv = (j < L_) ? p * ex2f_(et[j] * LOG2E_) : 0.f;
    #pragma unroll
    for (int off = 16; off; off >>= 1) fv += __shfl_xor_sync(0xffffffffu, fv, off);
    float denom = (C2 + lg2f_(fv)) * LN2_;

    if (lane == 0) g_llh[b] = num - denom;
}

// ---------------------------------------------------------------------------
__global__ void finalize_kernel(float* __restrict__ out) {
    int t = threadIdx.x;                     // 64
    float v = g_llh[t];
    #pragma unroll
    for (int off = 16; off; off >>= 1) v += __shfl_down_sync(0xffffffffu, v, off);
    __shared__ float r[2];
    if ((t & 31) == 0) r[t >> 5] = v;
    __syncthreads();
    if (t == 0) out[0] = -((r[0] + r[1]) * (1.0f / B_));
}

// ---------------------------------------------------------------------------
extern "C" void kernel_launch(void* const* d_in, const int* in_sizes, int n_in,
                              void* d_out, int out_size)
{
    const float* hs    = (const float*)d_in[0];
    const float* gamma = (const float*)d_in[1];
    const float* beta  = (const float*)d_in[2];
    const float* W1    = (const float*)d_in[3];
    const float* b1    = (const float*)d_in[4];
    const float* W2    = (const float*)d_in[5];
    const float* b2    = (const float*)d_in[6];
    const float* st    = (const float*)d_in[7];
    const float* et    = (const float*)d_in[8];
    const float* trans = (const float*)d_in[9];
    const int*   labels= (const int*)d_in[10];
    const int*   am    = (const int*)d_in[11];

    cudaFuncSetAttribute(gemm1_tc_kernel,
                         cudaFuncAttributeMaxDynamicSharedMemorySize, GEMM1_SMEM);

    ln_norm_kernel<<<NTOK / 32, 256>>>(hs, gamma, beta);
    w1_transpose_kernel<<<dim3(HD2 / 32, H_ / 32), dim3(32, 8)>>>(W1);
    gemm1_tc_kernel<<<dim3(HD2 / 128, NTOK / 128), 256, GEMM1_SMEM>>>(b1, W2);
    crf_kernel<<<B_, 32>>>(st, et, trans, b2, labels, am);
    finalize_kernel<<<1, 64>>>((float*)d_out);
}

// round 15
// speedup vs baseline: 1.1560x; 1.1560x over previous
#include <cuda_runtime.h>
#include <cuda_bf16.h>
#include <cuda_fp16.h>
#include <cuda_fp8.h>
#include <math.h>
#include <stdint.h>

#define B_    64
#define S_    512
#define H_    1024
#define HD2   512
#define L_    9
#define NTOK  (B_*S_)
#define EPS_  1e-5f
#define LOG2E_ 1.4426950408889634f
#define LN2_   0.6931471805599453f
#define W1SCL  64.0f
#define W1INV  0.015625f

// ---------------- device scratch (no allocation allowed) -------------------
__device__ uint8_t g_x8[(size_t)NTOK * H_];          // LN-normalized X, e4m3
__device__ uint8_t g_w1t8[(size_t)HD2 * H_];         // (W1*64)^T e4m3 [N][K]
__device__ float g_emp[4][(size_t)NTOK * L_];        // partial emissions per n-slice
__device__ float g_em[(size_t)NTOK * L_];            // emissions fp32
__device__ float g_llh[B_];

// ---------------------------------------------------------------------------
__device__ __forceinline__ float ex2f_(float x){ float y; asm("ex2.approx.ftz.f32 %0,%1;":"=f"(y):"f"(x)); return y; }
__device__ __forceinline__ float lg2f_(float x){ float y; asm("lg2.approx.ftz.f32 %0,%1;":"=f"(y):"f"(x)); return y; }

__device__ __forceinline__ void cp16s(uint32_t dst, const void* src){
    asm volatile("cp.async.cg.shared.global [%0], [%1], 16;" :: "r"(dst), "l"(src));
}
__device__ __forceinline__ void ldsm4(uint32_t* r, uint32_t addr){
    asm volatile("ldmatrix.sync.aligned.m8n8.x4.shared.b16 {%0,%1,%2,%3}, [%4];"
        : "=r"(r[0]), "=r"(r[1]), "=r"(r[2]), "=r"(r[3]) : "r"(addr));
}
__device__ __forceinline__ uint16_t f2e4m3x2_(float hi, float lo){
    uint16_t r;
    asm("cvt.rn.satfinite.e4m3x2.f32 %0, %1, %2;" : "=h"(r) : "f"(hi), "f"(lo));
    return r;
}
// tanh-form GELU: overflow-safe, ~0.1-0.3% off exact erf GELU — below the
// fp8 quantization noise already present. Measured ~35us faster than erff.
__device__ __forceinline__ float gelu_(float c){
    float u  = 0.7978845608028654f * fmaf(0.044715f * c, c * c, c);
    float ez = ex2f_(u * 2.8853900817779268f);          // e^{2u}
    float th = 1.0f - __fdividef(2.0f, ez + 1.0f);
    return 0.5f * c * (1.0f + th);
}

// ---------------------------------------------------------------------------
// Kernel 1: LayerNorm -> normalized e4m3 X. Warp-per-row, barrier-free.
// ---------------------------------------------------------------------------
__global__ void __launch_bounds__(256) ln_norm_kernel(
    const float* __restrict__ hs,
    const float* __restrict__ gamma,
    const float* __restrict__ beta)
{
    const int warp = threadIdx.x >> 5;
    const int lane = threadIdx.x & 31;

    #pragma unroll
    for (int rr = 0; rr < 4; rr++) {
        const int row = blockIdx.x * 32 + warp * 4 + rr;
        const float4* p = (const float4*)(hs + (size_t)row * H_);
        float4 v[8];
        float s = 0.f, ss = 0.f;
        #pragma unroll
        for (int j = 0; j < 8; j++) {
            v[j] = p[lane + 32 * j];
            s  += v[j].x + v[j].y + v[j].z + v[j].w;
            ss += v[j].x*v[j].x + v[j].y*v[j].y + v[j].z*v[j].z + v[j].w*v[j].w;
        }
        #pragma unroll
        for (int off = 16; off; off >>= 1) {
            s  += __shfl_xor_sync(0xffffffffu, s,  off);
            ss += __shfl_xor_sync(0xffffffffu, ss, off);
        }
        const float mu   = s * (1.0f / H_);
        const float rstd = rsqrtf(ss * (1.0f / H_) - mu * mu + EPS_);

        uint32_t* dst = (uint32_t*)(g_x8 + (size_t)row * H_);
        #pragma unroll
        for (int j = 0; j < 8; j++) {
            const int q = lane + 32 * j;
            float4 g4 = ((const float4*)gamma)[q];
            float4 b4 = ((const float4*)beta)[q];
            float o0 = (v[j].x - mu) * rstd * g4.x + b4.x;
            float o1 = (v[j].y - mu) * rstd * g4.y + b4.y;
            float o2 = (v[j].z - mu) * rstd * g4.z + b4.z;
            float o3 = (v[j].w - mu) * rstd * g4.w + b4.w;
            uint32_t lo = f2e4m3x2_(o1, o0);
            uint32_t hi = f2e4m3x2_(o3, o2);
            dst[q] = lo | (hi << 16);
        }
    }
}

// ---------------------------------------------------------------------------
// Kernel 2: W1 [K=1024][N=512] fp32 -> (W1*64)^T e4m3 [N][K]
// ---------------------------------------------------------------------------
__global__ void w1_transpose_kernel(const float* __restrict__ W1)
{
    __shared__ float tile[32][33];
    const int n0 = blockIdx.x * 32, k0 = blockIdx.y * 32;
    const int tx = threadIdx.x, ty = threadIdx.y;   // (32, 8)
    #pragma unroll
    for (int i = 0; i < 4; i++)
        tile[ty + 8*i][tx] = W1[(size_t)(k0 + ty + 8*i) * HD2 + n0 + tx];
    __syncthreads();
    #pragma unroll
    for (int i = 0; i < 4; i++) {
        uint16_t p = f2e4m3x2_(0.f, tile[tx][ty + 8*i] * W1SCL);
        g_w1t8[(size_t)(n0 + ty + 8*i) * H_ + k0 + tx] = (uint8_t)(p & 0xff);
    }
}

// ---------------------------------------------------------------------------
// Kernel 3: FUSED GEMM1+GELU+GEMM2-partial (R13 structure, fast GELU).
// ---------------------------------------------------------------------------
#define ROWB    80                       // 64B data + 16B pad
#define TILE_A  (128 * ROWB)             // 10240
#define TILE_BB (128 * ROWB)             // 10240
#define STG_B   (TILE_A + TILE_BB)       // 20480
#define NSTG    3
#define NKT     16                       // 1024B / 64B
#define PIPE_B  (NSTG * STG_B)           // 61440
#define W2_OFF  PIPE_B                   // [128][12] floats = 6144 B
#define B1_OFF  (W2_OFF + 6144)          // 128 floats = 512 B
#define STGRED  (B1_OFF + 512)           // [4][32][12] floats = 6144 B
#define GEMM1_SMEM (STGRED + 6144)       // 74240

__global__ void __launch_bounds__(256, 3) gemm1_tc_kernel(
    const float* __restrict__ b1, const float* __restrict__ W2)
{
    extern __shared__ __align__(16) char dsm[];
    const uint32_t sbase = (uint32_t)__cvta_generic_to_shared(dsm);
    float* w2s = (float*)(dsm + W2_OFF);     // [128][12]
    float* b1s = (float*)(dsm + B1_OFF);     // [128]
    float* stg = (float*)(dsm + STGRED);     // [4][32][12]

    const int tid  = threadIdx.x;
    const int m0   = blockIdx.y * 128;
    const int n0   = blockIdx.x * 128;       // h-col slice base
    const int warp = tid >> 5, lane = tid & 31;
    const int wm   = warp & 1;               // M half (64 rows)
    const int wn   = warp >> 1;              // N quarter (32 cols)

    // preload W2 slice + b1 slice
    for (int i = tid; i < 128 * L_; i += 256)
        w2s[(i / L_) * 12 + (i % L_)] = W2[(size_t)(n0 + i / L_) * L_ + (i % L_)];
    if (tid < 128) b1s[tid] = b1[n0 + tid];

    uint32_t offA[4], offB[2];
    {
        const int rA = (lane & 15);
        const int cA = (lane >> 4);
        #pragma unroll
        for (int mt = 0; mt < 4; mt++)
            offA[mt] = (uint32_t)((wm * 64 + mt * 16 + rA) * ROWB + cA * 16);
        const int rB = (lane & 7) + ((lane >> 4) << 3);
        const int cB = (lane >> 3) & 1;
        #pragma unroll
        for (int p = 0; p < 2; p++)
            offB[p] = (uint32_t)(TILE_A + (wn * 32 + p * 16 + rB) * ROWB + cB * 16);
    }

    // loaders: 1 thread per row; tid<128 -> A row, tid>=128 -> B row. 4x16B.
    const int lrow = tid & 127;
    const int isB  = tid >> 7;
    const uint8_t* Sg = isB ? (g_w1t8 + (size_t)(n0 + lrow) * H_)
                            : (g_x8   + (size_t)(m0 + lrow) * H_);
    const uint32_t dS = sbase + isB * TILE_A + lrow * ROWB;

    uint32_t acc[4][4][2];                 // f16x2 accumulators
    #pragma unroll
    for (int mt = 0; mt < 4; mt++)
        #pragma unroll
        for (int nt = 0; nt < 4; nt++) { acc[mt][nt][0] = 0u; acc[mt][nt][1] = 0u; }

    #pragma unroll
    for (int p = 0; p < 2; ++p) {
        const uint32_t sg = p * STG_B;
        #pragma unroll
        for (int c = 0; c < 4; c++)
            cp16s(dS + sg + c * 16, Sg + p * 64 + c * 16);
        asm volatile("cp.async.commit_group;");
    }

    for (int t = 0; t < NKT; ++t) {
        if (t < NKT - 1) asm volatile("cp.async.wait_group 1;");
        else             asm volatile("cp.async.wait_group 0;");
        __syncthreads();

        const uint32_t sS = sbase + (t % NSTG) * STG_B;
        #pragma unroll
        for (int kt = 0; kt < 2; ++kt) {            // two k32 steps per 64B row
            uint32_t a[4][4], b[2][4];
            #pragma unroll
            for (int mt = 0; mt < 4; mt++) ldsm4(a[mt], sS + offA[mt] + kt * 32);
            #pragma unroll
            for (int p = 0; p < 2; p++)    ldsm4(b[p],  sS + offB[p]  + kt * 32);
            #pragma unroll
            for (int mt = 0; mt < 4; mt++)
                #pragma unroll
                for (int nt = 0; nt < 4; nt++) {
                    const uint32_t b0  = b[nt >> 1][(nt & 1) * 2];
                    const uint32_t b1r = b[nt >> 1][(nt & 1) * 2 + 1];
                    asm volatile(
                        "mma.sync.aligned.m16n8k32.row.col.f16.e4m3.e4m3.f16 "
                        "{%0,%1},{%2,%3,%4,%5},{%6,%7},{%0,%1};"
                        : "+r"(acc[mt][nt][0]), "+r"(acc[mt][nt][1])
                        : "r"(a[mt][0]), "r"(a[mt][1]), "r"(a[mt][2]), "r"(a[mt][3]),
                          "r"(b0), "r"(b1r));
                }
        }

        if (t + 2 < NKT) {
            const uint32_t sg = ((t + 2) % NSTG) * STG_B;
            const int k0 = (t + 2) * 64;
            #pragma unroll
            for (int c = 0; c < 4; c++)
                cp16s(dS + sg + c * 16, Sg + k0 + c * 16);
            asm volatile("cp.async.commit_group;");
        }
    }

    // ---- fused epilogue: fast GELU + dot with W2 slice + staged reduction ----
    const int r = lane >> 2, tig = lane & 3;
    #pragma unroll
    for (int mt = 0; mt < 4; mt++) {
        float e0[L_], e1[L_];
        #pragma unroll
        for (int l = 0; l < L_; l++) { e0[l] = 0.f; e1[l] = 0.f; }

        #pragma unroll
        for (int nt = 0; nt < 4; nt++) {
            const int c0 = wn * 32 + nt * 8 + 2 * tig;   // local h-col
            const float bx = b1s[c0], by = b1s[c0 + 1];
            float2 f01 = __half22float2(*(__half2*)&acc[mt][nt][0]);
            float2 f23 = __half22float2(*(__half2*)&acc[mt][nt][1]);
            float g00 = gelu_(f01.x * W1INV + bx);
            float g01 = gelu_(f01.y * W1INV + by);
            float g10 = gelu_(f23.x * W1INV + bx);
            float g11 = gelu_(f23.y * W1INV + by);
            const float* w0 = &w2s[c0 * 12];
            const float* w1 = &w2s[(c0 + 1) * 12];
            #pragma unroll
            for (int l = 0; l < L_; l++) {
                e0[l] = fmaf(g00, w0[l], fmaf(g01, w1[l], e0[l]));
                e1[l] = fmaf(g10, w0[l], fmaf(g11, w1[l], e1[l]));
            }
        }
        #pragma unroll
        for (int l = 0; l < L_; l++) {
            e0[l] += __shfl_xor_sync(0xffffffffu, e0[l], 1);
            e0[l] += __shfl_xor_sync(0xffffffffu, e0[l], 2);
            e1[l] += __shfl_xor_sync(0xffffffffu, e1[l], 1);
            e1[l] += __shfl_xor_sync(0xffffffffu, e1[l], 2);
        }
        if (tig == 0) {
            float* s0 = &stg[(wn * 32 + wm * 16 + r) * 12];
            float* s1 = &stg[(wn * 32 + wm * 16 + r + 8) * 12];
            #pragma unroll
            for (int l = 0; l < L_; l++) { s0[l] = e0[l]; s1[l] = e1[l]; }
        }
        __syncthreads();
        for (int idx = tid; idx < 32 * L_; idx += 256) {
            const int wr = idx / L_, l = idx % L_;
            const int wmm = wr >> 4, rr = wr & 15;
            float v = stg[(0 * 32 + wr) * 12 + l] + stg[(1 * 32 + wr) * 12 + l]
                    + stg[(2 * 32 + wr) * 12 + l] + stg[(3 * 32 + wr) * 12 + l];
            const int row = m0 + wmm * 64 + mt * 16 + rr;
            g_emp[blockIdx.x][(size_t)row * L_ + l] = v;
        }
        __syncthreads();
    }
}

// ---------------------------------------------------------------------------
// Kernel 4: sum the 4 partial-emission slices + b2
// ---------------------------------------------------------------------------
__global__ void em_sum_kernel(const float* __restrict__ b2)
{
    const int l   = threadIdx.x;                        // 0..8
    const int tok = blockIdx.x * 32 + threadIdx.y;      // 32 tokens/block
    const size_t i = (size_t)tok * L_ + l;
    g_em[i] = g_emp[0][i] + g_emp[1][i] + g_emp[2][i] + g_emp[3][i] + b2[l];
}

// ---------------------------------------------------------------------------
// Kernel 5: CRF (R13 version: reads pre-summed g_em).
// ---------------------------------------------------------------------------
__global__ void crf_kernel(const float* __restrict__ st,
                           const float* __restrict__ et,
                           const float* __restrict__ trans,
                           const int*   __restrict__ labels,
                           const int*   __restrict__ am)
{
    const int b    = blockIdx.x;
    const int lane = threadIdx.x;
    const float* em  = g_em + (size_t)b * S_ * L_;
    const int*   lab = labels + (size_t)b * S_;
    const int*   amk = am     + (size_t)b * S_;

    uint32_t mword[16];
    #pragma unroll
    for (int c = 0; c < 16; c++) {
        int t = c * 32 + lane;
        int l = lab[t];
        bool mk = (l != -100) && (amk[t] == 1);
        mword[c] = __ballot_sync(0xffffffffu, mk);
    }

    float part = 0.f;
    int   cnt  = 0;
    for (int t = lane; t < S_; t += 32) {
        bool rw = (mword[t >> 5] >> (t & 31)) & 1;
        bool mk = (t == 0) ? true : rw;
        if (mk) cnt++;
        if (t > 0 && rw) {
            int tp = lab[t - 1]; if (tp == -100) tp = 0;
            int tc = lab[t];     if (tc == -100) tc = 0;
            part += trans[tp * L_ + tc] + em[t * L_ + tc];
        }
    }
    #pragma unroll
    for (int off = 16; off; off >>= 1) {
        part += __shfl_down_sync(0xffffffffu, part, off);
        cnt  += __shfl_down_sync(0xffffffffu, cnt,  off);
    }
    float num = 0.f;
    if (lane == 0) {
        int tg0 = lab[0]; if (tg0 == -100) tg0 = 0;
        num = part + st[tg0] + em[tg0];
        int se = cnt - 1;
        int lt = lab[se]; if (lt == -100) lt = 0;
        num += et[lt];
    }

    const int j = lane;
    float c_[L_];
    #pragma unroll
    for (int i = 0; i < L_; i++)
        c_[i] = (j < L_) ? ex2f_(trans[i * L_ + j] * LOG2E_) : 0.f;

    float p  = (j < L_) ? ex2f_((st[j] + em[j]) * LOG2E_) : 0.f;
    float C2 = 0.f;

    float cur[8], nxt[8];
    #pragma unroll
    for (int i = 0; i < 8; i++)
        cur[i] = (j < L_) ? em[(1 + i) * L_ + j] : 0.f;

    for (int tb = 1; tb < S_; tb += 8) {
        #pragma unroll
        for (int i = 0; i < 8; i++) {
            int tn = tb + 8 + i;
            nxt[i] = (tn < S_ && j < L_) ? em[tn * L_ + j] : 0.f;
        }
        {
            float m = __shfl_sync(0xffffffffu, p, 0);
            int e = (__float_as_int(m) >> 23) & 255;
            float sc = __int_as_float((254 - e) << 23);
            p *= sc;
            C2 += (float)(e - 127);
        }
        #pragma unroll
        for (int i = 0; i < 8; i++) {
            int t = tb + i;
            if (t < S_) {
                float eem = ex2f_(cur[i] * LOG2E_);
                float pa[L_];
                #pragma unroll
                for (int q = 0; q < L_; q++) pa[q] = __shfl_sync(0xffffffffu, p, q);
                float s01 = fmaf(pa[1], c_[1], pa[0] * c_[0]);
                float s23 = fmaf(pa[3], c_[3], pa[2] * c_[2]);
                float s45 = fmaf(pa[5], c_[5], pa[4] * c_[4]);
                float s67 = fmaf(pa[7], c_[7], pa[6] * c_[6]);
                float s8  = pa[8] * c_[8];
                float s   = (s01 + s23) + (s45 + s67) + s8;
                float pn  = s * eem;
                bool mk = (mword[t >> 5] >> (t & 31)) & 1;
                p = mk ? pn : p;
            }
        }
        #pragma unroll
        for (int i = 0; i < 8; i++) cur[i] = nxt[i];
    }

    float fv = (j < L_) ? p * ex2f_(et[j] * LOG2E_) : 0.f;
    #pragma unroll
    for (int off = 16; off; off >>= 1) fv += __shfl_xor_sync(0xffffffffu, fv, off);
    float denom = (C2 + lg2f_(fv)) * LN2_;

    if (lane == 0) g_llh[b] = num - denom;
}

// ---------------------------------------------------------------------------
__global__ void finalize_kernel(float* __restrict__ out) {
    int t = threadIdx.x;                     // 64
    float v = g_llh[t];
    #pragma unroll
    for (int off = 16; off; off >>= 1) v += __shfl_down_sync(0xffffffffu, v, off);
    __shared__ float r[2];
    if ((t & 31) == 0) r[t >> 5] = v;
    __syncthreads();
    if (t == 0) out[0] = -((r[0] + r[1]) * (1.0f / B_));
}

// ---------------------------------------------------------------------------
extern "C" void kernel_launch(void* const* d_in, const int* in_sizes, int n_in,
                              void* d_out, int out_size)
{
    const float* hs    = (const float*)d_in[0];
    const float* gamma = (const float*)d_in[1];
    const float* beta  = (const float*)d_in[2];
    const float* W1    = (const float*)d_in[3];
    const float* b1    = (const float*)d_in[4];
    const float* W2    = (const float*)d_in[5];
    const float* b2    = (const float*)d_in[6];
    const float* st    = (const float*)d_in[7];
    const float* et    = (const float*)d_in[8];
    const float* trans = (const float*)d_in[9];
    const int*   labels= (const int*)d_in[10];
    const int*   am    = (const int*)d_in[11];

    cudaFuncSetAttribute(gemm1_tc_kernel,
                         cudaFuncAttributeMaxDynamicSharedMemorySize, GEMM1_SMEM);

    ln_norm_kernel<<<NTOK / 32, 256>>>(hs, gamma, beta);
    w1_transpose_kernel<<<dim3(HD2 / 32, H_ / 32), dim3(32, 8)>>>(W1);
    gemm1_tc_kernel<<<dim3(HD2 / 128, NTOK / 128), 256, GEMM1_SMEM>>>(b1, W2);
    em_sum_kernel<<<NTOK / 32, dim3(L_, 32)>>>(b2);
    crf_kernel<<<B_, 32>>>(st, et, trans, labels, am);
    finalize_kernel<<<1, 64>>>((float*)d_out);
}